// round 3
// baseline (speedup 1.0000x reference)
#include <cuda_runtime.h>

#define NB 2
#define N1 4096
#define N2 16384
#define CF 64
#define KNN 8

// Grid for spatial hashing
#define G    48
#define NC   (G * G * G)        // 110592 cells per batch
#define NCT  (NB * NC)          // 221184
#define GH   0.25f              // cell size
#define GOFF 6.0f               // grid covers [-6,6)
#define GINV 4.0f               // 1/GH
#define SCAN_BLOCKS (NCT / 1024)  // 216 per array

// ---------------- scratch (__device__ globals per allocation rules) --------
__device__ int    g_tcnt[NCT], g_ts1[NCT], g_tbs[SCAN_BLOCKS], g_ts2[SCAN_BLOCKS];
__device__ int    g_qcnt[NCT], g_qs1[NCT], g_qbs[SCAN_BLOCKS], g_qs2[SCAN_BLOCKS];
__device__ int    g_tcur[NCT], g_qcur[NCT];
__device__ int    g_tcid[NB * N1], g_qcid[NB * N2];
__device__ float4 g_spts[NB * N1];        // cell-sorted points, w = index bits
__device__ int    g_qord[NB * N2];        // sorted pos -> original local query idx
__device__ float  g_gtab[NB * N1 * CF];   // W1_feat@feat + W1_xyz@xyz1 + b1
__device__ int    g_idx[NB * N2 * KNN];   // knn indices, stored in SORTED query order

__device__ __forceinline__ int cellcoord(float v) {
    int c = __float2int_rd((v + GOFF) * GINV);
    return min(max(c, 0), G - 1);
}

// ---------------------------------------------------------------------------
// zero counters / cursors (device arrays persist across graph replays)
// ---------------------------------------------------------------------------
__global__ void zero_kernel() {
    int i = blockIdx.x * 256 + threadIdx.x;
    if (i < NCT) { g_tcnt[i] = 0; g_qcnt[i] = 0; g_tcur[i] = 0; g_qcur[i] = 0; }
}

// ---------------------------------------------------------------------------
// cell assignment + histograms
// ---------------------------------------------------------------------------
__global__ void assign_t(const float* __restrict__ xyz1) {
    int i = blockIdx.x * 256 + threadIdx.x;
    if (i >= NB * N1) return;
    int b = i >> 12, j = i & (N1 - 1);
    const float* p = xyz1 + (size_t)b * 3 * N1;
    int cx = cellcoord(p[j]), cy = cellcoord(p[N1 + j]), cz = cellcoord(p[2 * N1 + j]);
    int cid = b * NC + (cz * G + cy) * G + cx;
    g_tcid[i] = cid;
    atomicAdd(&g_tcnt[cid], 1);
}

__global__ void assign_q(const float* __restrict__ xyz2) {
    int i = blockIdx.x * 256 + threadIdx.x;
    if (i >= NB * N2) return;
    int b = i >> 14, j = i & (N2 - 1);
    const float* p = xyz2 + (size_t)b * 3 * N2;
    int cx = cellcoord(p[j]), cy = cellcoord(p[N2 + j]), cz = cellcoord(p[2 * N2 + j]);
    int cid = b * NC + (cz * G + cy) * G + cx;
    g_qcid[i] = cid;
    atomicAdd(&g_qcnt[cid], 1);
}

// ---------------------------------------------------------------------------
// two-level exclusive scan. Level 1: 1024-wide blocks; level 2: block sums.
// Base offset of cell cid = s1[cid] + s2[cid >> 10].
// ---------------------------------------------------------------------------
__global__ void __launch_bounds__(1024) scan1_kernel() {
    int which = blockIdx.x >= SCAN_BLOCKS;                 // 0 = targets, 1 = queries
    int blk = which ? blockIdx.x - SCAN_BLOCKS : blockIdx.x;
    const int* cnt = which ? g_qcnt : g_tcnt;
    int* s1 = which ? g_qs1 : g_ts1;
    int* bs = which ? g_qbs : g_tbs;

    __shared__ int sh[1024];
    int tid = threadIdx.x;
    int v = cnt[blk * 1024 + tid];
    sh[tid] = v;
    __syncthreads();
#pragma unroll
    for (int off = 1; off < 1024; off <<= 1) {
        int t = (tid >= off) ? sh[tid - off] : 0;
        __syncthreads();
        sh[tid] += t;
        __syncthreads();
    }
    s1[blk * 1024 + tid] = sh[tid] - v;                    // exclusive
    if (tid == 1023) bs[blk] = sh[1023];
}

__global__ void scan2_kernel() {
    int which = blockIdx.x;
    const int* bs = which ? g_qbs : g_tbs;
    int* s2 = which ? g_qs2 : g_ts2;

    __shared__ int sh[256];
    int tid = threadIdx.x;
    int v = (tid < SCAN_BLOCKS) ? bs[tid] : 0;
    sh[tid] = v;
    __syncthreads();
#pragma unroll
    for (int off = 1; off < 256; off <<= 1) {
        int t = (tid >= off) ? sh[tid - off] : 0;
        __syncthreads();
        sh[tid] += t;
        __syncthreads();
    }
    if (tid < SCAN_BLOCKS) s2[tid] = sh[tid] - v;
}

// ---------------------------------------------------------------------------
// scatter into cell-sorted order
// ---------------------------------------------------------------------------
__global__ void scatter_t(const float* __restrict__ xyz1) {
    int i = blockIdx.x * 256 + threadIdx.x;
    if (i >= NB * N1) return;
    int b = i >> 12, j = i & (N1 - 1);
    const float* p = xyz1 + (size_t)b * 3 * N1;
    float x = p[j], y = p[N1 + j], z = p[2 * N1 + j];
    int cid = g_tcid[i];
    int pos = g_ts1[cid] + g_ts2[cid >> 10] + atomicAdd(&g_tcur[cid], 1);
    g_spts[pos] = make_float4(x, y, z, __int_as_float(j));
}

__global__ void scatter_q() {
    int i = blockIdx.x * 256 + threadIdx.x;
    if (i >= NB * N2) return;
    int j = i & (N2 - 1);
    int cid = g_qcid[i];
    int pos = g_qs1[cid] + g_qs2[cid >> 10] + atomicAdd(&g_qcur[cid], 1);
    g_qord[pos] = j;
}

// ---------------------------------------------------------------------------
// per-target transform  g[b][j][o] = sum_c W1[o][c]*in[c] + b1[o]
// ---------------------------------------------------------------------------
__global__ void __launch_bounds__(256) gmat_kernel(const float* __restrict__ feat1,
                                                   const float* __restrict__ xyz1,
                                                   const float* __restrict__ W1,
                                                   const float* __restrict__ b1) {
    __shared__ __align__(16) float sIn[67 * 64];
    __shared__ float sW[64 * 67];
    __shared__ float sB[64];

    int b  = blockIdx.x >> 6;
    int j0 = (blockIdx.x & 63) * 64;
    int t  = threadIdx.x;

    for (int i = t; i < 64 * 67; i += 256) sW[i] = W1[i];
    if (t < 64) sB[t] = b1[t];

    const float* fb = feat1 + (size_t)b * CF * N1;
    for (int i = t; i < 64 * 64; i += 256) {
        int c = i >> 6, j = i & 63;
        sIn[c * 64 + j] = fb[c * N1 + j0 + j];
    }
    const float* xb = xyz1 + (size_t)b * 3 * N1;
    if (t < 3 * 64) {
        int c = t >> 6, j = t & 63;
        sIn[(64 + c) * 64 + j] = xb[c * N1 + j0 + j];
    }
    __syncthreads();

    int o = t & 63, jg = t >> 6;
    float acc[16];
    float bb = sB[o];
#pragma unroll
    for (int ii = 0; ii < 16; ii++) acc[ii] = bb;

    for (int c = 0; c < 67; c++) {
        float w = sW[o * 67 + c];
        const float4* in4 = (const float4*)(sIn + c * 64 + jg * 16);
#pragma unroll
        for (int q4 = 0; q4 < 4; q4++) {
            float4 v = in4[q4];
            acc[q4 * 4 + 0] = fmaf(w, v.x, acc[q4 * 4 + 0]);
            acc[q4 * 4 + 1] = fmaf(w, v.y, acc[q4 * 4 + 1]);
            acc[q4 * 4 + 2] = fmaf(w, v.z, acc[q4 * 4 + 2]);
            acc[q4 * 4 + 3] = fmaf(w, v.w, acc[q4 * 4 + 3]);
        }
    }

    float* gp = g_gtab + ((size_t)b * N1 + j0 + jg * 16) * CF + o;
#pragma unroll
    for (int ii = 0; ii < 16; ii++) gp[ii * CF] = acc[ii];
}

// ---------------------------------------------------------------------------
// grid KNN: expanding Chebyshev shells; stop when dk[7] <= (r*h)^2.
// Queries processed in cell-sorted order (warp-coherent shells & cells).
// ---------------------------------------------------------------------------
__device__ __forceinline__ void ins8(float (&dk)[8], int (&ik)[8], float d, int j) {
    dk[7] = d; ik[7] = j;
#pragma unroll
    for (int s = 7; s >= 1; --s) {
        if (dk[s] < dk[s - 1]) {
            float tf = dk[s - 1]; dk[s - 1] = dk[s]; dk[s] = tf;
            int   ti = ik[s - 1]; ik[s - 1] = ik[s]; ik[s] = ti;
        }
    }
}

__device__ __forceinline__ void scan_cell(int cid, float qx, float qy, float qz,
                                          float (&dk)[8], int (&ik)[8]) {
    int n = g_tcnt[cid];
    if (!n) return;
    int base = g_ts1[cid] + g_ts2[cid >> 10];
    for (int ii = 0; ii < n; ii++) {
        float4 p = g_spts[base + ii];
        float ddx = p.x - qx, ddy = p.y - qy, ddz = p.z - qz;
        float d = fmaf(ddz, ddz, fmaf(ddy, ddy, ddx * ddx));
        if (d < dk[7]) ins8(dk, ik, d, __float_as_int(p.w));
    }
}

__global__ void __launch_bounds__(256) knn_grid(const float* __restrict__ xyz2) {
    int pos = blockIdx.x * 256 + threadIdx.x;   // 0 .. NB*N2-1 (sorted order)
    int b = pos >> 14;
    int q = g_qord[pos];

    const float* xq = xyz2 + (size_t)b * 3 * N2;
    float qx = xq[q], qy = xq[N2 + q], qz = xq[2 * N2 + q];
    int cx = cellcoord(qx), cy = cellcoord(qy), cz = cellcoord(qz);

    float dk[8]; int ik[8];
#pragma unroll
    for (int r = 0; r < 8; r++) { dk[r] = 3.4e38f; ik[r] = 0; }

    const int cbase = b * NC;

    for (int r = 0; r < G; r++) {
        int x0 = max(cx - r, 0), x1 = min(cx + r, G - 1);
        int y0 = max(cy - r, 0), y1 = min(cy + r, G - 1);
        int z0 = max(cz - r, 0), z1 = min(cz + r, G - 1);
        for (int zz = z0; zz <= z1; zz++) {
            int adz = (zz > cz) ? zz - cz : cz - zz;
            for (int yy = y0; yy <= y1; yy++) {
                int ady = (yy > cy) ? yy - cy : cy - yy;
                int rowc = cbase + (zz * G + yy) * G;
                if (adz == r || ady == r) {
                    for (int xx = x0; xx <= x1; xx++)
                        scan_cell(rowc + xx, qx, qy, qz, dk, ik);
                } else {
                    if (cx - r >= 0) scan_cell(rowc + cx - r, qx, qy, qz, dk, ik);
                    if (cx + r < G)  scan_cell(rowc + cx + r, qx, qy, qz, dk, ik);
                }
            }
        }
        float bound = GH * (float)r;
        if (dk[7] <= bound * bound) break;   // unscanned cells are >= r*h away
    }

    int4* op4 = (int4*)(g_idx + (size_t)pos * KNN);
    op4[0] = make_int4(ik[0], ik[1], ik[2], ik[3]);
    op4[1] = make_int4(ik[4], ik[5], ik[6], ik[7]);
}

// ---------------------------------------------------------------------------
// finalize (4 sub-threads per query, 16 channels each), sorted query order.
// h_n = lrelu(g[idx_n] - W1_xyz @ q);  w_j[n] = W2[j].h_n  (b2 cancels);
// softmax over n; dot with flow.
// ---------------------------------------------------------------------------
__device__ __forceinline__ float softmax_dot(const float (&w)[8],
                                             const float* __restrict__ f,
                                             const int (&ik)[8]) {
    float m = w[0];
#pragma unroll
    for (int n = 1; n < 8; n++) m = fmaxf(m, w[n]);
    float s = 0.f, acc = 0.f;
#pragma unroll
    for (int n = 0; n < 8; n++) {
        float e = __expf(w[n] - m);
        s += e;
        acc = fmaf(e, __ldg(f + ik[n]), acc);
    }
    return acc / s;
}

__global__ void __launch_bounds__(256) up_kernel(const float* __restrict__ xyz2,
                                                 const float* __restrict__ flow,
                                                 const float* __restrict__ W1,
                                                 const float* __restrict__ W2,
                                                 float* __restrict__ out) {
    __shared__ float sW2[3 * 64];   // [j][o]
    __shared__ float sWx[64 * 3];   // [o][c]  (xyz columns of W1)
    int t = threadIdx.x;
    if (t < 192) sW2[t] = W2[t];
    if (t < 192) { int o = t / 3, c = t - o * 3; sWx[t] = W1[o * 67 + 64 + c]; }
    __syncthreads();

    int qL = t >> 2;          // 0..63
    int s  = t & 3;
    int b  = blockIdx.x >> 8;
    int pos = (int)(((blockIdx.x & 255) << 6) + qL) + b * N2;  // sorted position
    int q  = g_qord[pos];                                      // original local idx

    const float* xq = xyz2 + (size_t)b * 3 * N2;
    float qx = xq[q], qy = xq[N2 + q], qz = xq[2 * N2 + q];

    const int* ip = g_idx + (size_t)pos * KNN;                 // sorted order read
    int ik[8];
    {
        int4 a  = ((const int4*)ip)[0];
        int4 c4 = ((const int4*)ip)[1];
        ik[0] = a.x;  ik[1] = a.y;  ik[2] = a.z;  ik[3] = a.w;
        ik[4] = c4.x; ik[5] = c4.y; ik[6] = c4.z; ik[7] = c4.w;
    }

    const float* gb = g_gtab + (size_t)b * N1 * CF;

    float a0[8], a1[8], a2[8];
#pragma unroll
    for (int n = 0; n < 8; n++) { a0[n] = 0.f; a1[n] = 0.f; a2[n] = 0.f; }

#pragma unroll
    for (int oo = 0; oo < 4; oo++) {
        int o4 = s * 4 + oo;
        int ob = o4 * 4;
        float uu[4], wa[4], wb[4], wc[4];
#pragma unroll
        for (int i = 0; i < 4; i++) {
            int o = ob + i;
            uu[i] = fmaf(sWx[o * 3 + 2], qz, fmaf(sWx[o * 3 + 1], qy, sWx[o * 3] * qx));
            wa[i] = sW2[o];
            wb[i] = sW2[64 + o];
            wc[i] = sW2[128 + o];
        }
#pragma unroll
        for (int n = 0; n < 8; n++) {
            float4 g4 = ((const float4*)(gb + (size_t)ik[n] * CF))[o4];
            float h;
            h = g4.x - uu[0]; h = h >= 0.f ? h : 0.1f * h;
            a0[n] = fmaf(wa[0], h, a0[n]); a1[n] = fmaf(wb[0], h, a1[n]); a2[n] = fmaf(wc[0], h, a2[n]);
            h = g4.y - uu[1]; h = h >= 0.f ? h : 0.1f * h;
            a0[n] = fmaf(wa[1], h, a0[n]); a1[n] = fmaf(wb[1], h, a1[n]); a2[n] = fmaf(wc[1], h, a2[n]);
            h = g4.z - uu[2]; h = h >= 0.f ? h : 0.1f * h;
            a0[n] = fmaf(wa[2], h, a0[n]); a1[n] = fmaf(wb[2], h, a1[n]); a2[n] = fmaf(wc[2], h, a2[n]);
            h = g4.w - uu[3]; h = h >= 0.f ? h : 0.1f * h;
            a0[n] = fmaf(wa[3], h, a0[n]); a1[n] = fmaf(wb[3], h, a1[n]); a2[n] = fmaf(wc[3], h, a2[n]);
        }
    }

    const unsigned FULL = 0xffffffffu;
#pragma unroll
    for (int d = 1; d <= 2; d <<= 1) {
#pragma unroll
        for (int n = 0; n < 8; n++) {
            a0[n] += __shfl_xor_sync(FULL, a0[n], d);
            a1[n] += __shfl_xor_sync(FULL, a1[n], d);
            a2[n] += __shfl_xor_sync(FULL, a2[n], d);
        }
    }

    if (s == 0) {
        const float* fb = flow + (size_t)b * 3 * N1;
        float* ob_ = out + (size_t)b * 3 * N2;
        ob_[q]          = softmax_dot(a0, fb, ik);
        ob_[N2 + q]     = softmax_dot(a1, fb + N1, ik);
        ob_[2 * N2 + q] = softmax_dot(a2, fb + 2 * N1, ik);
    }
}

// ---------------------------------------------------------------------------
extern "C" void kernel_launch(void* const* d_in, const int* in_sizes, int n_in,
                              void* d_out, int out_size) {
    const float* xyz1  = (const float*)d_in[0];
    const float* xyz2  = (const float*)d_in[1];
    const float* feat1 = (const float*)d_in[2];
    const float* flow  = (const float*)d_in[3];
    const float* W1    = (const float*)d_in[4];
    const float* b1    = (const float*)d_in[5];
    const float* W2    = (const float*)d_in[6];
    // b2 (d_in[7]) unused: constant shift cancels in softmax over k.
    float* out = (float*)d_out;

    zero_kernel<<<(NCT + 255) / 256, 256>>>();
    assign_t<<<(NB * N1 + 255) / 256, 256>>>(xyz1);
    assign_q<<<(NB * N2 + 255) / 256, 256>>>(xyz2);
    scan1_kernel<<<2 * SCAN_BLOCKS, 1024>>>();
    scan2_kernel<<<2, 256>>>();
    scatter_t<<<(NB * N1 + 255) / 256, 256>>>(xyz1);
    scatter_q<<<(NB * N2 + 255) / 256, 256>>>();
    gmat_kernel<<<NB * 64, 256>>>(feat1, xyz1, W1, b1);
    knn_grid<<<NB * N2 / 256, 256>>>(xyz2);
    up_kernel<<<NB * 256, 256>>>(xyz2, flow, W1, W2, out);
}

// round 4
// speedup vs baseline: 3.2243x; 3.2243x over previous
#include <cuda_runtime.h>

#define NB 2
#define N1 4096
#define N2 16384
#define CF 64
#define KNN 8

// Scratch (static __device__ arrays per allocation rules)
__device__ float4 g_pts[NB * N1];            // x, y, z, |p|^2
__device__ float  g_gtab[NB * N1 * CF];      // W1_feat@feat + W1_xyz@xyz1 + b1
__device__ int    g_idx[NB * N2 * KNN];      // knn indices

// ---------------------------------------------------------------------------
// Kernel 1: pack xyz1 into float4 (x,y,z,|p|^2)
// ---------------------------------------------------------------------------
__global__ void pack_kernel(const float* __restrict__ xyz1) {
    int i = blockIdx.x * blockDim.x + threadIdx.x;
    if (i >= NB * N1) return;
    int b = i / N1, j = i - b * N1;
    const float* p = xyz1 + (size_t)b * 3 * N1;
    float x = p[j], y = p[N1 + j], z = p[2 * N1 + j];
    g_pts[i] = make_float4(x, y, z, x * x + y * y + z * z);
}

// ---------------------------------------------------------------------------
// Kernel 2: per-target transform  g[b][j][o] = sum_c W1[o][c]*in[c] + b1[o]
// ---------------------------------------------------------------------------
__global__ void __launch_bounds__(256) gmat_kernel(const float* __restrict__ feat1,
                                                   const float* __restrict__ xyz1,
                                                   const float* __restrict__ W1,
                                                   const float* __restrict__ b1) {
    __shared__ __align__(16) float sIn[67 * 64];
    __shared__ float sW[64 * 67];
    __shared__ float sB[64];

    int b  = blockIdx.x >> 6;
    int j0 = (blockIdx.x & 63) * 64;
    int t  = threadIdx.x;

    for (int i = t; i < 64 * 67; i += 256) sW[i] = W1[i];
    if (t < 64) sB[t] = b1[t];

    const float* fb = feat1 + (size_t)b * CF * N1;
    for (int i = t; i < 64 * 64; i += 256) {
        int c = i >> 6, j = i & 63;
        sIn[c * 64 + j] = fb[c * N1 + j0 + j];
    }
    const float* xb = xyz1 + (size_t)b * 3 * N1;
    if (t < 3 * 64) {
        int c = t >> 6, j = t & 63;
        sIn[(64 + c) * 64 + j] = xb[c * N1 + j0 + j];
    }
    __syncthreads();

    int o = t & 63, jg = t >> 6;
    float acc[16];
    float bb = sB[o];
#pragma unroll
    for (int ii = 0; ii < 16; ii++) acc[ii] = bb;

    for (int c = 0; c < 67; c++) {
        float w = sW[o * 67 + c];
        const float4* in4 = (const float4*)(sIn + c * 64 + jg * 16);
#pragma unroll
        for (int q4 = 0; q4 < 4; q4++) {
            float4 v = in4[q4];
            acc[q4 * 4 + 0] = fmaf(w, v.x, acc[q4 * 4 + 0]);
            acc[q4 * 4 + 1] = fmaf(w, v.y, acc[q4 * 4 + 1]);
            acc[q4 * 4 + 2] = fmaf(w, v.z, acc[q4 * 4 + 2]);
            acc[q4 * 4 + 3] = fmaf(w, v.w, acc[q4 * 4 + 3]);
        }
    }

    float* gp = g_gtab + ((size_t)b * N1 + j0 + jg * 16) * CF + o;
#pragma unroll
    for (int ii = 0; ii < 16; ii++) gp[ii * CF] = acc[ii];
}

// ---------------------------------------------------------------------------
// Kernel 3: brute-force top-8 KNN, 1 thread/query, unroll-8 inner loop.
// Score s = |t|^2 - 2*q.t (same ordering as reference distance).
// All lanes read the same smem word per target -> LDS broadcast.
// ---------------------------------------------------------------------------
__device__ __forceinline__ void ins8(float (&dk)[8], int (&ik)[8], float d, int j) {
    dk[7] = d; ik[7] = j;
#pragma unroll
    for (int s = 7; s >= 1; --s) {
        if (dk[s] < dk[s - 1]) {
            float tf = dk[s - 1]; dk[s - 1] = dk[s]; dk[s] = tf;
            int   ti = ik[s - 1]; ik[s - 1] = ik[s]; ik[s] = ti;
        }
    }
}

__global__ void __launch_bounds__(256) knn_kernel(const float* __restrict__ xyz2) {
    __shared__ __align__(16) float4 sP[2048];

    int b = blockIdx.x >> 6;
    int q = (blockIdx.x & 63) * 256 + threadIdx.x;

    const float* xq = xyz2 + (size_t)b * 3 * N2;
    float qx = xq[q], qy = xq[N2 + q], qz = xq[2 * N2 + q];
    float mx = -2.f * qx, my = -2.f * qy, mz = -2.f * qz;

    float dk[8]; int ik[8];
#pragma unroll
    for (int s = 0; s < 8; s++) { dk[s] = 3.4e38f; ik[s] = 0; }
    float dk7 = 3.4e38f;

    const float4* P = g_pts + b * N1;

    for (int tile = 0; tile < N1; tile += 2048) {
        __syncthreads();
        for (int i = threadIdx.x; i < 2048; i += 256) sP[i] = P[tile + i];
        __syncthreads();

#pragma unroll 2
        for (int j = 0; j < 2048; j += 8) {
            float d[8];
#pragma unroll
            for (int u = 0; u < 8; u++) {
                float4 p = sP[j + u];
                d[u] = fmaf(mz, p.z, fmaf(my, p.y, fmaf(mx, p.x, p.w)));
            }
            // depth-3 min tree over the 8 candidates
            float m0 = fminf(d[0], d[1]), m1 = fminf(d[2], d[3]);
            float m2 = fminf(d[4], d[5]), m3 = fminf(d[6], d[7]);
            float dmin = fminf(fminf(m0, m1), fminf(m2, m3));
            if (dmin < dk7) {
                int jb = tile + j;
#pragma unroll
                for (int u = 0; u < 8; u++) {
                    if (d[u] < dk7) { ins8(dk, ik, d[u], jb + u); dk7 = dk[7]; }
                }
            }
        }
    }

    int4* op4 = (int4*)(g_idx + ((size_t)b * N2 + q) * KNN);
    op4[0] = make_int4(ik[0], ik[1], ik[2], ik[3]);
    op4[1] = make_int4(ik[4], ik[5], ik[6], ik[7]);
}

// ---------------------------------------------------------------------------
// Kernel 4: finalize, 4 sub-threads per query (16 channels each).
// h_n = lrelu(g[idx_n] - W1_xyz @ q);  w_j[n] = W2[j].h_n  (b2 cancels);
// softmax over n; dot with flow.
// ---------------------------------------------------------------------------
__device__ __forceinline__ float softmax_dot(const float (&w)[8],
                                             const float* __restrict__ f,
                                             const int (&ik)[8]) {
    float m = w[0];
#pragma unroll
    for (int n = 1; n < 8; n++) m = fmaxf(m, w[n]);
    float s = 0.f, acc = 0.f;
#pragma unroll
    for (int n = 0; n < 8; n++) {
        float e = __expf(w[n] - m);
        s += e;
        acc = fmaf(e, __ldg(f + ik[n]), acc);
    }
    return acc / s;
}

__global__ void __launch_bounds__(256) up_kernel(const float* __restrict__ xyz2,
                                                 const float* __restrict__ flow,
                                                 const float* __restrict__ W1,
                                                 const float* __restrict__ W2,
                                                 float* __restrict__ out) {
    __shared__ float sW2[3 * 64];   // [j][o]
    __shared__ float sWx[64 * 3];   // [o][c]  (xyz columns of W1)
    int t = threadIdx.x;
    if (t < 192) sW2[t] = W2[t];
    if (t < 192) { int o = t / 3, c = t - o * 3; sWx[t] = W1[o * 67 + 64 + c]; }
    __syncthreads();

    int qL = t >> 2;          // 0..63
    int s  = t & 3;
    int b  = blockIdx.x >> 8; // 256 blocks per batch
    int q  = ((blockIdx.x & 255) << 6) + qL;

    const float* xq = xyz2 + (size_t)b * 3 * N2;
    float qx = xq[q], qy = xq[N2 + q], qz = xq[2 * N2 + q];

    const int* ip = g_idx + ((size_t)b * N2 + q) * KNN;
    int ik[8];
    {
        int4 a  = ((const int4*)ip)[0];
        int4 c4 = ((const int4*)ip)[1];
        ik[0] = a.x;  ik[1] = a.y;  ik[2] = a.z;  ik[3] = a.w;
        ik[4] = c4.x; ik[5] = c4.y; ik[6] = c4.z; ik[7] = c4.w;
    }

    const float* gb = g_gtab + (size_t)b * N1 * CF;

    float a0[8], a1[8], a2[8];
#pragma unroll
    for (int n = 0; n < 8; n++) { a0[n] = 0.f; a1[n] = 0.f; a2[n] = 0.f; }

    // sub-thread s owns o4 blocks [4s, 4s+4) = channels [16s, 16s+16)
#pragma unroll
    for (int oo = 0; oo < 4; oo++) {
        int o4 = s * 4 + oo;
        int ob = o4 * 4;
        float uu[4], wa[4], wb[4], wc[4];
#pragma unroll
        for (int i = 0; i < 4; i++) {
            int o = ob + i;
            uu[i] = fmaf(sWx[o * 3 + 2], qz, fmaf(sWx[o * 3 + 1], qy, sWx[o * 3] * qx));
            wa[i] = sW2[o];
            wb[i] = sW2[64 + o];
            wc[i] = sW2[128 + o];
        }
#pragma unroll
        for (int n = 0; n < 8; n++) {
            float4 g4 = ((const float4*)(gb + (size_t)ik[n] * CF))[o4];
            float h;
            h = g4.x - uu[0]; h = h >= 0.f ? h : 0.1f * h;
            a0[n] = fmaf(wa[0], h, a0[n]); a1[n] = fmaf(wb[0], h, a1[n]); a2[n] = fmaf(wc[0], h, a2[n]);
            h = g4.y - uu[1]; h = h >= 0.f ? h : 0.1f * h;
            a0[n] = fmaf(wa[1], h, a0[n]); a1[n] = fmaf(wb[1], h, a1[n]); a2[n] = fmaf(wc[1], h, a2[n]);
            h = g4.z - uu[2]; h = h >= 0.f ? h : 0.1f * h;
            a0[n] = fmaf(wa[2], h, a0[n]); a1[n] = fmaf(wb[2], h, a1[n]); a2[n] = fmaf(wc[2], h, a2[n]);
            h = g4.w - uu[3]; h = h >= 0.f ? h : 0.1f * h;
            a0[n] = fmaf(wa[3], h, a0[n]); a1[n] = fmaf(wb[3], h, a1[n]); a2[n] = fmaf(wc[3], h, a2[n]);
        }
    }

    // reduce the 4 sub-threads' partials (lanes 4k..4k+3 hold one query)
    const unsigned FULL = 0xffffffffu;
#pragma unroll
    for (int d = 1; d <= 2; d <<= 1) {
#pragma unroll
        for (int n = 0; n < 8; n++) {
            a0[n] += __shfl_xor_sync(FULL, a0[n], d);
            a1[n] += __shfl_xor_sync(FULL, a1[n], d);
            a2[n] += __shfl_xor_sync(FULL, a2[n], d);
        }
    }

    if (s == 0) {
        const float* fb = flow + (size_t)b * 3 * N1;
        float* ob_ = out + (size_t)b * 3 * N2;
        ob_[q]          = softmax_dot(a0, fb, ik);
        ob_[N2 + q]     = softmax_dot(a1, fb + N1, ik);
        ob_[2 * N2 + q] = softmax_dot(a2, fb + 2 * N1, ik);
    }
}

// ---------------------------------------------------------------------------
extern "C" void kernel_launch(void* const* d_in, const int* in_sizes, int n_in,
                              void* d_out, int out_size) {
    const float* xyz1  = (const float*)d_in[0];
    const float* xyz2  = (const float*)d_in[1];
    const float* feat1 = (const float*)d_in[2];
    const float* flow  = (const float*)d_in[3];
    const float* W1    = (const float*)d_in[4];
    const float* b1    = (const float*)d_in[5];
    const float* W2    = (const float*)d_in[6];
    // b2 (d_in[7]) unused: constant shift cancels in softmax over k.
    float* out = (float*)d_out;

    pack_kernel<<<(NB * N1 + 255) / 256, 256>>>(xyz1);
    gmat_kernel<<<NB * 64, 256>>>(feat1, xyz1, W1, b1);
    knn_kernel<<<NB * 64, 256>>>(xyz2);
    up_kernel<<<NB * 256, 256>>>(xyz2, flow, W1, W2, out);
}

// round 5
// speedup vs baseline: 4.0873x; 1.2676x over previous
#include <cuda_runtime.h>

#define NB 2
#define N1 4096
#define N2 16384
#define CF 64
#define KNN 8
#define NT_KNN (NB * N2 * 2)   // 65536 knn threads (2 subs per query)
#define RING 128

// Scratch (static __device__ arrays per allocation rules)
__device__ float4 g_pts[NB * N1];            // x, y, z, |p|^2
__device__ float  g_gtab[NB * N1 * CF];      // W1_feat@feat + W1_xyz@xyz1 + b1
__device__ int    g_idx[NB * N2 * KNN];      // knn indices (arbitrary order)
__device__ int2   g_ring[RING * NT_KNN];     // per-thread candidate rings (64MB)

// ---------------------------------------------------------------------------
// Kernel 1: pack xyz1 into float4 (x,y,z,|p|^2)
// ---------------------------------------------------------------------------
__global__ void pack_kernel(const float* __restrict__ xyz1) {
    int i = blockIdx.x * blockDim.x + threadIdx.x;
    if (i >= NB * N1) return;
    int b = i / N1, j = i - b * N1;
    const float* p = xyz1 + (size_t)b * 3 * N1;
    float x = p[j], y = p[N1 + j], z = p[2 * N1 + j];
    g_pts[i] = make_float4(x, y, z, x * x + y * y + z * z);
}

// ---------------------------------------------------------------------------
// Kernel 2: per-target transform  g[b][j][o] = sum_c W1[o][c]*in[c] + b1[o]
// ---------------------------------------------------------------------------
__global__ void __launch_bounds__(256) gmat_kernel(const float* __restrict__ feat1,
                                                   const float* __restrict__ xyz1,
                                                   const float* __restrict__ W1,
                                                   const float* __restrict__ b1) {
    __shared__ __align__(16) float sIn[67 * 64];
    __shared__ float sW[64 * 67];
    __shared__ float sB[64];

    int b  = blockIdx.x >> 6;
    int j0 = (blockIdx.x & 63) * 64;
    int t  = threadIdx.x;

    for (int i = t; i < 64 * 67; i += 256) sW[i] = W1[i];
    if (t < 64) sB[t] = b1[t];

    const float* fb = feat1 + (size_t)b * CF * N1;
    for (int i = t; i < 64 * 64; i += 256) {
        int c = i >> 6, j = i & 63;
        sIn[c * 64 + j] = fb[c * N1 + j0 + j];
    }
    const float* xb = xyz1 + (size_t)b * 3 * N1;
    if (t < 3 * 64) {
        int c = t >> 6, j = t & 63;
        sIn[(64 + c) * 64 + j] = xb[c * N1 + j0 + j];
    }
    __syncthreads();

    int o = t & 63, jg = t >> 6;
    float acc[16];
    float bb = sB[o];
#pragma unroll
    for (int ii = 0; ii < 16; ii++) acc[ii] = bb;

    for (int c = 0; c < 67; c++) {
        float w = sW[o * 67 + c];
        const float4* in4 = (const float4*)(sIn + c * 64 + jg * 16);
#pragma unroll
        for (int q4 = 0; q4 < 4; q4++) {
            float4 v = in4[q4];
            acc[q4 * 4 + 0] = fmaf(w, v.x, acc[q4 * 4 + 0]);
            acc[q4 * 4 + 1] = fmaf(w, v.y, acc[q4 * 4 + 1]);
            acc[q4 * 4 + 2] = fmaf(w, v.z, acc[q4 * 4 + 2]);
            acc[q4 * 4 + 3] = fmaf(w, v.w, acc[q4 * 4 + 3]);
        }
    }

    float* gp = g_gtab + ((size_t)b * N1 + j0 + jg * 16) * CF + o;
#pragma unroll
    for (int ii = 0; ii < 16; ii++) gp[ii * CF] = acc[ii];
}

// ---------------------------------------------------------------------------
// Kernel 3: top-8 KNN, 2 sub-threads per query, branchless FMNMX top-8
// distances + candidate ring; exact threshold via shfl bitonic merge;
// emit ring entries <= threshold. Order of emitted indices is arbitrary
// (downstream softmax+sum is permutation invariant).
// ---------------------------------------------------------------------------
__device__ __forceinline__ void insd(float (&dk)[8], float dd) {
#pragma unroll
    for (int r = 0; r < 8; r++) {
        float lo = fminf(dk[r], dd);
        dd = fmaxf(dk[r], dd);
        dk[r] = lo;
    }
}

__global__ void __launch_bounds__(256) knn_kernel(const float* __restrict__ xyz2) {
    __shared__ __align__(16) float4 sP[2048];
    __shared__ int scnt[128];

    int t    = threadIdx.x;
    int s    = t & 1;          // sub-thread: scans targets j == s (mod 2)
    int qL   = t >> 1;         // 0..127 query within block
    int b    = blockIdx.x >> 7;
    int q    = ((blockIdx.x & 127) << 7) + qL;
    int gtid = blockIdx.x * 256 + t;

    if (t < 128) scnt[t] = 0;

    const float* xq = xyz2 + (size_t)b * 3 * N2;
    float qx = xq[q], qy = xq[N2 + q], qz = xq[2 * N2 + q];
    float mx = -2.f * qx, my = -2.f * qy, mz = -2.f * qz;

    float dk[8];
#pragma unroll
    for (int r = 0; r < 8; r++) dk[r] = 3.4e38f;
    float dk7 = 3.4e38f;
    int cnt = 0;

    const float4* P = g_pts + b * N1;

    for (int tile = 0; tile < 2; tile++) {
        __syncthreads();
#pragma unroll
        for (int r = 0; r < 8; r++) sP[t * 8 + r] = P[tile * 2048 + t * 8 + r];
        __syncthreads();

        for (int i = 0; i < 1024; i += 8) {
            float d[8];
#pragma unroll
            for (int u = 0; u < 8; u++) {
                float4 p = sP[2 * (i + u) + s];
                d[u] = fmaf(mz, p.z, fmaf(my, p.y, fmaf(mx, p.x, p.w)));
            }
            float m0 = fminf(d[0], d[1]), m1 = fminf(d[2], d[3]);
            float m2 = fminf(d[4], d[5]), m3 = fminf(d[6], d[7]);
            float dmin = fminf(fminf(m0, m1), fminf(m2, m3));
            if (dmin < dk7) {
#pragma unroll
                for (int u = 0; u < 8; u++) {
                    if (d[u] < dk7) {
                        insd(dk, d[u]);
                        dk7 = dk[7];
                        int m = tile * 2048 + 2 * (i + u) + s;
                        g_ring[min(cnt, RING - 1) * NT_KNN + gtid] =
                            make_int2(__float_as_int(d[u]), m);
                        cnt++;
                    }
                }
            }
        }
    }

    // Exact 8th-smallest across the two subs: merged-8-smallest of two sorted
    // ascending 8-lists a,b is {min(a[r], b[7-r])}; threshold = its max.
    const unsigned FULL = 0xffffffffu;
    float od[8];
#pragma unroll
    for (int r = 0; r < 8; r++) od[r] = __shfl_xor_sync(FULL, dk[r], 1);
    float th = fminf(dk[0], od[7]);
#pragma unroll
    for (int r = 1; r < 8; r++) th = fmaxf(th, fminf(dk[r], od[7 - r]));

    // Emit: every global top-8 member was inserted (hence recorded) by its sub.
    int n = min(cnt, RING);
    int base = (b * N2 + q) * KNN;
    for (int r = 0; r < n; r++) {
        int2 e = g_ring[r * NT_KNN + gtid];
        if (__int_as_float(e.x) <= th) {
            int slot = atomicAdd(&scnt[qL], 1);
            if (slot < 8) g_idx[base + slot] = e.y;
        }
    }
}

// ---------------------------------------------------------------------------
// Kernel 4: finalize, 4 sub-threads per query (16 channels each).
// h_n = lrelu(g[idx_n] - W1_xyz @ q);  w_j[n] = W2[j].h_n  (b2 cancels);
// softmax over n; dot with flow.
// ---------------------------------------------------------------------------
__device__ __forceinline__ float softmax_dot(const float (&w)[8],
                                             const float* __restrict__ f,
                                             const int (&ik)[8]) {
    float m = w[0];
#pragma unroll
    for (int n = 1; n < 8; n++) m = fmaxf(m, w[n]);
    float s = 0.f, acc = 0.f;
#pragma unroll
    for (int n = 0; n < 8; n++) {
        float e = __expf(w[n] - m);
        s += e;
        acc = fmaf(e, __ldg(f + ik[n]), acc);
    }
    return acc / s;
}

__global__ void __launch_bounds__(256) up_kernel(const float* __restrict__ xyz2,
                                                 const float* __restrict__ flow,
                                                 const float* __restrict__ W1,
                                                 const float* __restrict__ W2,
                                                 float* __restrict__ out) {
    __shared__ float sW2[3 * 64];   // [j][o]
    __shared__ float sWx[64 * 3];   // [o][c]  (xyz columns of W1)
    int t = threadIdx.x;
    if (t < 192) sW2[t] = W2[t];
    if (t < 192) { int o = t / 3, c = t - o * 3; sWx[t] = W1[o * 67 + 64 + c]; }
    __syncthreads();

    int qL = t >> 2;          // 0..63
    int s  = t & 3;
    int b  = blockIdx.x >> 8; // 256 blocks per batch
    int q  = ((blockIdx.x & 255) << 6) + qL;

    const float* xq = xyz2 + (size_t)b * 3 * N2;
    float qx = xq[q], qy = xq[N2 + q], qz = xq[2 * N2 + q];

    const int* ip = g_idx + ((size_t)b * N2 + q) * KNN;
    int ik[8];
    {
        int4 a  = ((const int4*)ip)[0];
        int4 c4 = ((const int4*)ip)[1];
        ik[0] = a.x;  ik[1] = a.y;  ik[2] = a.z;  ik[3] = a.w;
        ik[4] = c4.x; ik[5] = c4.y; ik[6] = c4.z; ik[7] = c4.w;
    }

    const float* gb = g_gtab + (size_t)b * N1 * CF;

    float a0[8], a1[8], a2[8];
#pragma unroll
    for (int n = 0; n < 8; n++) { a0[n] = 0.f; a1[n] = 0.f; a2[n] = 0.f; }

    // sub-thread s owns o4 blocks [4s, 4s+4) = channels [16s, 16s+16)
#pragma unroll
    for (int oo = 0; oo < 4; oo++) {
        int o4 = s * 4 + oo;
        int ob = o4 * 4;
        float uu[4], wa[4], wb[4], wc[4];
#pragma unroll
        for (int i = 0; i < 4; i++) {
            int o = ob + i;
            uu[i] = fmaf(sWx[o * 3 + 2], qz, fmaf(sWx[o * 3 + 1], qy, sWx[o * 3] * qx));
            wa[i] = sW2[o];
            wb[i] = sW2[64 + o];
            wc[i] = sW2[128 + o];
        }
#pragma unroll
        for (int n = 0; n < 8; n++) {
            float4 g4 = ((const float4*)(gb + (size_t)ik[n] * CF))[o4];
            float h;
            h = g4.x - uu[0]; h = h >= 0.f ? h : 0.1f * h;
            a0[n] = fmaf(wa[0], h, a0[n]); a1[n] = fmaf(wb[0], h, a1[n]); a2[n] = fmaf(wc[0], h, a2[n]);
            h = g4.y - uu[1]; h = h >= 0.f ? h : 0.1f * h;
            a0[n] = fmaf(wa[1], h, a0[n]); a1[n] = fmaf(wb[1], h, a1[n]); a2[n] = fmaf(wc[1], h, a2[n]);
            h = g4.z - uu[2]; h = h >= 0.f ? h : 0.1f * h;
            a0[n] = fmaf(wa[2], h, a0[n]); a1[n] = fmaf(wb[2], h, a1[n]); a2[n] = fmaf(wc[2], h, a2[n]);
            h = g4.w - uu[3]; h = h >= 0.f ? h : 0.1f * h;
            a0[n] = fmaf(wa[3], h, a0[n]); a1[n] = fmaf(wb[3], h, a1[n]); a2[n] = fmaf(wc[3], h, a2[n]);
        }
    }

    // reduce the 4 sub-threads' partials (lanes 4k..4k+3 hold one query)
    const unsigned FULL = 0xffffffffu;
#pragma unroll
    for (int d = 1; d <= 2; d <<= 1) {
#pragma unroll
        for (int n = 0; n < 8; n++) {
            a0[n] += __shfl_xor_sync(FULL, a0[n], d);
            a1[n] += __shfl_xor_sync(FULL, a1[n], d);
            a2[n] += __shfl_xor_sync(FULL, a2[n], d);
        }
    }

    if (s == 0) {
        const float* fb = flow + (size_t)b * 3 * N1;
        float* ob_ = out + (size_t)b * 3 * N2;
        ob_[q]          = softmax_dot(a0, fb, ik);
        ob_[N2 + q]     = softmax_dot(a1, fb + N1, ik);
        ob_[2 * N2 + q] = softmax_dot(a2, fb + 2 * N1, ik);
    }
}

// ---------------------------------------------------------------------------
extern "C" void kernel_launch(void* const* d_in, const int* in_sizes, int n_in,
                              void* d_out, int out_size) {
    const float* xyz1  = (const float*)d_in[0];
    const float* xyz2  = (const float*)d_in[1];
    const float* feat1 = (const float*)d_in[2];
    const float* flow  = (const float*)d_in[3];
    const float* W1    = (const float*)d_in[4];
    const float* b1    = (const float*)d_in[5];
    const float* W2    = (const float*)d_in[6];
    // b2 (d_in[7]) unused: constant shift cancels in softmax over k.
    float* out = (float*)d_out;

    pack_kernel<<<(NB * N1 + 255) / 256, 256>>>(xyz1);
    gmat_kernel<<<NB * 64, 256>>>(feat1, xyz1, W1, b1);
    knn_kernel<<<NB * 128, 256>>>(xyz2);
    up_kernel<<<NB * 256, 256>>>(xyz2, flow, W1, W2, out);
}

// round 6
// speedup vs baseline: 4.4610x; 1.0914x over previous
#include <cuda_runtime.h>

#define NB 2
#define N1 4096
#define N2 16384
#define CF 64
#define KNN 8

// Scratch (static __device__ arrays per allocation rules)
__device__ float4 g_pts[NB * N1];            // x, y, z, |p|^2
__device__ float  g_gtab[NB * N1 * CF];      // W1_feat@feat + W1_xyz@xyz1 + b1
__device__ int    g_idx[NB * N2 * KNN];      // knn indices (ascending distance)

// ---------------------------------------------------------------------------
// Kernel 1: pack xyz1 into float4 (x,y,z,|p|^2)
// ---------------------------------------------------------------------------
__global__ void pack_kernel(const float* __restrict__ xyz1) {
    int i = blockIdx.x * blockDim.x + threadIdx.x;
    if (i >= NB * N1) return;
    int b = i / N1, j = i - b * N1;
    const float* p = xyz1 + (size_t)b * 3 * N1;
    float x = p[j], y = p[N1 + j], z = p[2 * N1 + j];
    g_pts[i] = make_float4(x, y, z, x * x + y * y + z * z);
}

// ---------------------------------------------------------------------------
// Kernel 2: per-target transform  g[b][j][o] = sum_c W1[o][c]*in[c] + b1[o]
// ---------------------------------------------------------------------------
__global__ void __launch_bounds__(256) gmat_kernel(const float* __restrict__ feat1,
                                                   const float* __restrict__ xyz1,
                                                   const float* __restrict__ W1,
                                                   const float* __restrict__ b1) {
    __shared__ __align__(16) float sIn[67 * 64];
    __shared__ float sW[64 * 67];
    __shared__ float sB[64];

    int b  = blockIdx.x >> 6;
    int j0 = (blockIdx.x & 63) * 64;
    int t  = threadIdx.x;

    for (int i = t; i < 64 * 67; i += 256) sW[i] = W1[i];
    if (t < 64) sB[t] = b1[t];

    const float* fb = feat1 + (size_t)b * CF * N1;
    for (int i = t; i < 64 * 64; i += 256) {
        int c = i >> 6, j = i & 63;
        sIn[c * 64 + j] = fb[c * N1 + j0 + j];
    }
    const float* xb = xyz1 + (size_t)b * 3 * N1;
    if (t < 3 * 64) {
        int c = t >> 6, j = t & 63;
        sIn[(64 + c) * 64 + j] = xb[c * N1 + j0 + j];
    }
    __syncthreads();

    int o = t & 63, jg = t >> 6;
    float acc[16];
    float bb = sB[o];
#pragma unroll
    for (int ii = 0; ii < 16; ii++) acc[ii] = bb;

    for (int c = 0; c < 67; c++) {
        float w = sW[o * 67 + c];
        const float4* in4 = (const float4*)(sIn + c * 64 + jg * 16);
#pragma unroll
        for (int q4 = 0; q4 < 4; q4++) {
            float4 v = in4[q4];
            acc[q4 * 4 + 0] = fmaf(w, v.x, acc[q4 * 4 + 0]);
            acc[q4 * 4 + 1] = fmaf(w, v.y, acc[q4 * 4 + 1]);
            acc[q4 * 4 + 2] = fmaf(w, v.z, acc[q4 * 4 + 2]);
            acc[q4 * 4 + 3] = fmaf(w, v.w, acc[q4 * 4 + 3]);
        }
    }

    float* gp = g_gtab + ((size_t)b * N1 + j0 + jg * 16) * CF + o;
#pragma unroll
    for (int ii = 0; ii < 16; ii++) gp[ii * CF] = acc[ii];
}

// ---------------------------------------------------------------------------
// Kernel 3: top-8 KNN, ONE WARP PER QUERY.
// 32 lanes scan disjoint target slices; candidates found by ballot against
// the warp-shared true 8th-distance threshold; the sorted top-8 list is
// DISTRIBUTED across lanes 0..7 (lane r owns element r). Inserts are
// warp-uniform (ballot/ffs/shfl_up) — no divergent per-lane insert arms.
// Score s = |t|^2 - 2*q.t (same ordering as reference distance; strict <
// keeps earliest index on boundary ties, matching top_k tie-breaking).
// ---------------------------------------------------------------------------
__global__ void __launch_bounds__(512) knn_kernel(const float* __restrict__ xyz2) {
    __shared__ __align__(16) float4 sP[2048];   // 32 KB target tile

    const unsigned FULL = 0xffffffffu;
    int t    = threadIdx.x;
    int lane = t & 31;
    int w    = t >> 5;               // 0..15 : query within block
    int b    = blockIdx.x >> 10;     // 1024 blocks per batch
    int q    = ((blockIdx.x & 1023) << 4) + w;

    const float* xq = xyz2 + (size_t)b * 3 * N2;
    float qx = xq[q], qy = xq[N2 + q], qz = xq[2 * N2 + q];
    float mx = -2.f * qx, my = -2.f * qy, mz = -2.f * qz;

    float dk_own = 3.4e38f;          // lane r (r<8) holds list element r, ascending
    int   ik_own = 0;
    float dk7    = 3.4e38f;          // uniform copy of list element 7

    const float4* P = g_pts + b * N1;

    for (int tile = 0; tile < N1; tile += 2048) {
        __syncthreads();
#pragma unroll
        for (int r = 0; r < 4; r++) sP[t + r * 512] = P[tile + t + r * 512];
        __syncthreads();

        for (int i = 0; i < 64; i++) {
            float4 p = sP[i * 32 + lane];
            float d = fmaf(mz, p.z, fmaf(my, p.y, fmaf(mx, p.x, p.w)));
            unsigned m = __ballot_sync(FULL, d < dk7);
            while (m) {                      // warp-uniform loop
                int src = __ffs(m) - 1;
                m &= m - 1;
                float dc = __shfl_sync(FULL, d, src);
                if (dc < dk7) {              // uniform recheck vs tightened thr
                    int jc = tile + i * 32 + src;
                    // distributed sorted insert
                    unsigned gt = __ballot_sync(FULL, (lane < 8) && (dk_own > dc));
                    int pos = __ffs(gt) - 1;             // gt != 0 guaranteed
                    float upd = __shfl_up_sync(FULL, dk_own, 1);
                    int   upj = __shfl_up_sync(FULL, ik_own, 1);
                    if (lane < 8) {
                        if (lane == pos)      { dk_own = dc;  ik_own = jc;  }
                        else if (lane > pos)  { dk_own = upd; ik_own = upj; }
                    }
                    dk7 = __shfl_sync(FULL, dk_own, 7);
                }
            }
        }
    }

    if (lane < 8) g_idx[((size_t)b * N2 + q) * KNN + lane] = ik_own;
}

// ---------------------------------------------------------------------------
// Kernel 4: finalize, 4 sub-threads per query (16 channels each).
// h_n = lrelu(g[idx_n] - W1_xyz @ q);  w_j[n] = W2[j].h_n  (b2 cancels);
// softmax over n; dot with flow.
// ---------------------------------------------------------------------------
__device__ __forceinline__ float softmax_dot(const float (&w)[8],
                                             const float* __restrict__ f,
                                             const int (&ik)[8]) {
    float m = w[0];
#pragma unroll
    for (int n = 1; n < 8; n++) m = fmaxf(m, w[n]);
    float s = 0.f, acc = 0.f;
#pragma unroll
    for (int n = 0; n < 8; n++) {
        float e = __expf(w[n] - m);
        s += e;
        acc = fmaf(e, __ldg(f + ik[n]), acc);
    }
    return acc / s;
}

__global__ void __launch_bounds__(256) up_kernel(const float* __restrict__ xyz2,
                                                 const float* __restrict__ flow,
                                                 const float* __restrict__ W1,
                                                 const float* __restrict__ W2,
                                                 float* __restrict__ out) {
    __shared__ float sW2[3 * 64];   // [j][o]
    __shared__ float sWx[64 * 3];   // [o][c]  (xyz columns of W1)
    int t = threadIdx.x;
    if (t < 192) sW2[t] = W2[t];
    if (t < 192) { int o = t / 3, c = t - o * 3; sWx[t] = W1[o * 67 + 64 + c]; }
    __syncthreads();

    int qL = t >> 2;          // 0..63
    int s  = t & 3;
    int b  = blockIdx.x >> 8; // 256 blocks per batch
    int q  = ((blockIdx.x & 255) << 6) + qL;

    const float* xq = xyz2 + (size_t)b * 3 * N2;
    float qx = xq[q], qy = xq[N2 + q], qz = xq[2 * N2 + q];

    const int* ip = g_idx + ((size_t)b * N2 + q) * KNN;
    int ik[8];
    {
        int4 a  = ((const int4*)ip)[0];
        int4 c4 = ((const int4*)ip)[1];
        ik[0] = a.x;  ik[1] = a.y;  ik[2] = a.z;  ik[3] = a.w;
        ik[4] = c4.x; ik[5] = c4.y; ik[6] = c4.z; ik[7] = c4.w;
    }

    const float* gb = g_gtab + (size_t)b * N1 * CF;

    float a0[8], a1[8], a2[8];
#pragma unroll
    for (int n = 0; n < 8; n++) { a0[n] = 0.f; a1[n] = 0.f; a2[n] = 0.f; }

    // sub-thread s owns o4 blocks [4s, 4s+4) = channels [16s, 16s+16)
#pragma unroll
    for (int oo = 0; oo < 4; oo++) {
        int o4 = s * 4 + oo;
        int ob = o4 * 4;
        float uu[4], wa[4], wb[4], wc[4];
#pragma unroll
        for (int i = 0; i < 4; i++) {
            int o = ob + i;
            uu[i] = fmaf(sWx[o * 3 + 2], qz, fmaf(sWx[o * 3 + 1], qy, sWx[o * 3] * qx));
            wa[i] = sW2[o];
            wb[i] = sW2[64 + o];
            wc[i] = sW2[128 + o];
        }
#pragma unroll
        for (int n = 0; n < 8; n++) {
            float4 g4 = ((const float4*)(gb + (size_t)ik[n] * CF))[o4];
            float h;
            h = g4.x - uu[0]; h = h >= 0.f ? h : 0.1f * h;
            a0[n] = fmaf(wa[0], h, a0[n]); a1[n] = fmaf(wb[0], h, a1[n]); a2[n] = fmaf(wc[0], h, a2[n]);
            h = g4.y - uu[1]; h = h >= 0.f ? h : 0.1f * h;
            a0[n] = fmaf(wa[1], h, a0[n]); a1[n] = fmaf(wb[1], h, a1[n]); a2[n] = fmaf(wc[1], h, a2[n]);
            h = g4.z - uu[2]; h = h >= 0.f ? h : 0.1f * h;
            a0[n] = fmaf(wa[2], h, a0[n]); a1[n] = fmaf(wb[2], h, a1[n]); a2[n] = fmaf(wc[2], h, a2[n]);
            h = g4.w - uu[3]; h = h >= 0.f ? h : 0.1f * h;
            a0[n] = fmaf(wa[3], h, a0[n]); a1[n] = fmaf(wb[3], h, a1[n]); a2[n] = fmaf(wc[3], h, a2[n]);
        }
    }

    // reduce the 4 sub-threads' partials (lanes 4k..4k+3 hold one query)
    const unsigned FULL = 0xffffffffu;
#pragma unroll
    for (int d = 1; d <= 2; d <<= 1) {
#pragma unroll
        for (int n = 0; n < 8; n++) {
            a0[n] += __shfl_xor_sync(FULL, a0[n], d);
            a1[n] += __shfl_xor_sync(FULL, a1[n], d);
            a2[n] += __shfl_xor_sync(FULL, a2[n], d);
        }
    }

    if (s == 0) {
        const float* fb = flow + (size_t)b * 3 * N1;
        float* ob_ = out + (size_t)b * 3 * N2;
        ob_[q]          = softmax_dot(a0, fb, ik);
        ob_[N2 + q]     = softmax_dot(a1, fb + N1, ik);
        ob_[2 * N2 + q] = softmax_dot(a2, fb + 2 * N1, ik);
    }
}

// ---------------------------------------------------------------------------
extern "C" void kernel_launch(void* const* d_in, const int* in_sizes, int n_in,
                              void* d_out, int out_size) {
    const float* xyz1  = (const float*)d_in[0];
    const float* xyz2  = (const float*)d_in[1];
    const float* feat1 = (const float*)d_in[2];
    const float* flow  = (const float*)d_in[3];
    const float* W1    = (const float*)d_in[4];
    const float* b1    = (const float*)d_in[5];
    const float* W2    = (const float*)d_in[6];
    // b2 (d_in[7]) unused: constant shift cancels in softmax over k.
    float* out = (float*)d_out;

    pack_kernel<<<(NB * N1 + 255) / 256, 256>>>(xyz1);
    gmat_kernel<<<NB * 64, 256>>>(feat1, xyz1, W1, b1);
    knn_kernel<<<NB * 1024, 512>>>(xyz2);
    up_kernel<<<NB * 256, 256>>>(xyz2, flow, W1, W2, out);
}